// round 11
// baseline (speedup 1.0000x reference)
#include <cuda_runtime.h>
#include <cuda_bf16.h>
#include <math.h>
#include <stdint.h>

#define N_NODES  50000
#define N_EDGES  1000000
#define N_QUERY  100000
#define FDIM     256
#define KDIM     256
#define NB_SCAN  ((N_NODES + 255) / 256)   // 196

// ---------------- scratch (device globals: allocation-free) ----------------
__device__ float g_h[(size_t)N_NODES * FDIM];          // x @ W1
__device__ __nv_bfloat16 g_w1hi[KDIM * KDIM];          // W1^T [n][k]
__device__ __nv_bfloat16 g_w1lo[KDIM * KDIM];
__device__ float g_Q[(size_t)N_NODES * 4];
__device__ float g_P[(size_t)N_NODES * 4];
__device__ float g_Wc[256 * 4];
__device__ float g_bc[4];
__device__ int   g_counts[N_NODES];
__device__ int   g_cursor[N_NODES];
__device__ int   g_offsets[N_NODES + 1];
__device__ int   g_blocksums[NB_SCAN];
__device__ int2  g_edges[N_EDGES];

// ---------------- CSR build ----------------
__global__ void zero_kernel(int* __restrict__ counts, int* __restrict__ cursor)
{
    int i = blockIdx.x * blockDim.x + threadIdx.x;
    if (i < N_NODES) { counts[i] = 0; cursor[i] = 0; }
}

__global__ void count_kernel(const int* __restrict__ edge_index, int* __restrict__ counts)
{
    int e = blockIdx.x * blockDim.x + threadIdx.x;
    if (e < N_EDGES) atomicAdd(&counts[edge_index[N_EDGES + e]], 1);
}

__global__ void scan_part1(const int* __restrict__ counts, int* __restrict__ offsets,
                           int* __restrict__ blocksums)
{
    __shared__ int s[256];
    int i = blockIdx.x * 256 + threadIdx.x;
    int v = (i < N_NODES) ? counts[i] : 0;
    s[threadIdx.x] = v;
    __syncthreads();
    for (int off = 1; off < 256; off <<= 1) {
        int t = (threadIdx.x >= off) ? s[threadIdx.x - off] : 0;
        __syncthreads();
        s[threadIdx.x] += t;
        __syncthreads();
    }
    if (i < N_NODES) offsets[i] = s[threadIdx.x] - v;
    if (threadIdx.x == 255) blocksums[blockIdx.x] = s[255];
}

__global__ void scan_part2(int* __restrict__ blocksums)
{
    __shared__ int s[256];
    int i = threadIdx.x;
    int v = (i < NB_SCAN) ? blocksums[i] : 0;
    s[i] = v;
    __syncthreads();
    for (int off = 1; off < 256; off <<= 1) {
        int t = (i >= off) ? s[i - off] : 0;
        __syncthreads();
        s[i] += t;
        __syncthreads();
    }
    if (i < NB_SCAN) blocksums[i] = s[i] - v;
}

__global__ void scan_part3(int* __restrict__ offsets, const int* __restrict__ blocksums)
{
    int i = blockIdx.x * 256 + threadIdx.x;
    if (i < N_NODES) offsets[i] += blocksums[blockIdx.x];
    if (i == 0) offsets[N_NODES] = N_EDGES;
}

__global__ void fill_kernel(const int* __restrict__ edge_index,
                            const float* __restrict__ w,
                            const int* __restrict__ offsets,
                            int* __restrict__ cursor,
                            int2* __restrict__ edges)
{
    int e = blockIdx.x * blockDim.x + threadIdx.x;
    if (e >= N_EDGES) return;
    int s = edge_index[e];
    int d = edge_index[N_EDGES + e];
    int p = offsets[d] + atomicAdd(&cursor[d], 1);
    edges[p] = make_int2(s, __float_as_int(w[e]));
}

// ---------------- W1 [k][n] -> Wt [n][k] bf16 hi/lo ----------------
__global__ void split_w_kernel(const float* __restrict__ W,
                               __nv_bfloat16* __restrict__ bhi,
                               __nv_bfloat16* __restrict__ blo)
{
    int idx = blockIdx.x * 256 + threadIdx.x;   // n*256 + k
    int n = idx >> 8, k = idx & 255;
    float v = W[k * 256 + n];
    __nv_bfloat16 h = __float2bfloat16(v);
    bhi[idx] = h;
    blo[idx] = __float2bfloat16(v - __bfloat162float(h));
}

// ---------------- HMMA split-bf16 GEMM (ldmatrix + pipelined LDG) ----------------
#define PAD_K 40

__device__ __forceinline__ void mma_bf16(float* c, uint32_t a0, uint32_t a1,
                                         uint32_t a2, uint32_t a3,
                                         uint32_t b0, uint32_t b1) {
    asm volatile("mma.sync.aligned.m16n8k16.row.col.f32.bf16.bf16.f32 "
                 "{%0,%1,%2,%3}, {%4,%5,%6,%7}, {%8,%9}, {%0,%1,%2,%3};"
                 : "+f"(c[0]), "+f"(c[1]), "+f"(c[2]), "+f"(c[3])
                 : "r"(a0), "r"(a1), "r"(a2), "r"(a3), "r"(b0), "r"(b1));
}

__device__ __forceinline__ void ldsm_x4(uint32_t& r0, uint32_t& r1, uint32_t& r2, uint32_t& r3,
                                        uint32_t addr) {
    asm volatile("ldmatrix.sync.aligned.m8n8.x4.shared.b16 {%0,%1,%2,%3}, [%4];"
                 : "=r"(r0), "=r"(r1), "=r"(r2), "=r"(r3) : "r"(addr));
}
__device__ __forceinline__ void ldsm_x2(uint32_t& r0, uint32_t& r1, uint32_t addr) {
    asm volatile("ldmatrix.sync.aligned.m8n8.x2.shared.b16 {%0,%1}, [%2];"
                 : "=r"(r0), "=r"(r1) : "r"(addr));
}

__global__ __launch_bounds__(256)
void gemm_hmma(const float* __restrict__ X,
               const __nv_bfloat16* __restrict__ Bhi, const __nv_bfloat16* __restrict__ Blo,
               float* __restrict__ C, int M)
{
    __shared__ __nv_bfloat16 sAh[128 * PAD_K];
    __shared__ __nv_bfloat16 sAl[128 * PAD_K];
    __shared__ __nv_bfloat16 sBh[128 * PAD_K];
    __shared__ __nv_bfloat16 sBl[128 * PAD_K];

    int tid  = threadIdx.x;
    int wid  = tid >> 5;
    int lane = tid & 31;

    int row0 = blockIdx.x * 128;
    int col0 = blockIdx.y * 128;

    int wmi = wid & 1;
    int wni = wid >> 1;
    int m_base = wmi * 64;
    int n_base = wni * 32;

    // smem byte addresses (for ldmatrix)
    uint32_t bAh = (uint32_t)__cvta_generic_to_shared(sAh);
    uint32_t bAl = (uint32_t)__cvta_generic_to_shared(sAl);
    uint32_t bBh = (uint32_t)__cvta_generic_to_shared(sBh);
    uint32_t bBl = (uint32_t)__cvta_generic_to_shared(sBl);

    // per-lane ldmatrix row offsets
    int mrow = lane & 7;
    int selA = lane >> 3;                 // 0..3
    int arow_off = mrow + ((selA & 1) << 3);   // row within 16-block
    int akcol    = (selA >> 1) << 3;           // 0 or 8 (k offset)
    int selB = (lane >> 3) & 1;           // x2: matrices 0/1
    int brow_off = lane & 7;
    int bkcol    = selB << 3;

    float c[4][4][4];
#pragma unroll
    for (int mt = 0; mt < 4; mt++)
#pragma unroll
        for (int nt = 0; nt < 4; nt++)
#pragma unroll
            for (int j = 0; j < 4; j++) c[mt][nt][j] = 0.f;

    // staging registers
    float4 avreg[4];
    uint4  bhreg[2], blreg[2];

    // prefetch chunk 0
    {
#pragma unroll
        for (int r = 0; r < 4; r++) {
            int i   = tid + r * 256;
            int row = i >> 3, u = i & 7;
            int grow = row0 + row;
            avreg[r] = (grow < M) ? *(const float4*)(X + (size_t)grow * KDIM + u * 4)
                                  : make_float4(0.f, 0.f, 0.f, 0.f);
        }
#pragma unroll
        for (int r = 0; r < 2; r++) {
            int i   = tid + r * 256;
            int row = i >> 2, u = i & 3;
            bhreg[r] = ((const uint4*)(Bhi + (size_t)(col0 + row) * KDIM))[u];
            blreg[r] = ((const uint4*)(Blo + (size_t)(col0 + row) * KDIM))[u];
        }
    }

    for (int c0 = 0; c0 < 8; c0++) {
        // ---- store staged chunk into smem ----
#pragma unroll
        for (int r = 0; r < 4; r++) {
            int i   = tid + r * 256;
            int row = i >> 3, u = i & 7;
            float4 v = avreg[r];
            __nv_bfloat16 h0 = __float2bfloat16(v.x), h1 = __float2bfloat16(v.y);
            __nv_bfloat16 h2 = __float2bfloat16(v.z), h3 = __float2bfloat16(v.w);
            __nv_bfloat16 l0 = __float2bfloat16(v.x - __bfloat162float(h0));
            __nv_bfloat16 l1 = __float2bfloat16(v.y - __bfloat162float(h1));
            __nv_bfloat16 l2 = __float2bfloat16(v.z - __bfloat162float(h2));
            __nv_bfloat16 l3 = __float2bfloat16(v.w - __bfloat162float(h3));
            __nv_bfloat162* ah = (__nv_bfloat162*)(sAh + row * PAD_K + u * 4);
            __nv_bfloat162* al = (__nv_bfloat162*)(sAl + row * PAD_K + u * 4);
            ah[0] = __nv_bfloat162(h0, h1);
            ah[1] = __nv_bfloat162(h2, h3);
            al[0] = __nv_bfloat162(l0, l1);
            al[1] = __nv_bfloat162(l2, l3);
        }
#pragma unroll
        for (int r = 0; r < 2; r++) {
            int i   = tid + r * 256;
            int row = i >> 2, u = i & 3;
            *(uint4*)(sBh + row * PAD_K + u * 8) = bhreg[r];
            *(uint4*)(sBl + row * PAD_K + u * 8) = blreg[r];
        }
        __syncthreads();

        // ---- prefetch next chunk (overlaps with mma below) ----
        if (c0 < 7) {
            int k0n = (c0 + 1) * 32;
#pragma unroll
            for (int r = 0; r < 4; r++) {
                int i   = tid + r * 256;
                int row = i >> 3, u = i & 7;
                int grow = row0 + row;
                avreg[r] = (grow < M) ? *(const float4*)(X + (size_t)grow * KDIM + k0n + u * 4)
                                      : make_float4(0.f, 0.f, 0.f, 0.f);
            }
#pragma unroll
            for (int r = 0; r < 2; r++) {
                int i   = tid + r * 256;
                int row = i >> 2, u = i & 3;
                bhreg[r] = ((const uint4*)(Bhi + (size_t)(col0 + row) * KDIM + k0n))[u];
                blreg[r] = ((const uint4*)(Blo + (size_t)(col0 + row) * KDIM + k0n))[u];
            }
        }

        // ---- MMA on current chunk via ldmatrix ----
#pragma unroll
        for (int kk = 0; kk < 2; kk++) {
            int kb = kk * 16;
            uint32_t bh[4][2], bl[4][2];
#pragma unroll
            for (int nt = 0; nt < 4; nt++) {
                uint32_t off = (uint32_t)((n_base + nt * 8 + brow_off) * PAD_K + kb + bkcol) * 2;
                ldsm_x2(bh[nt][0], bh[nt][1], bBh + off);
                ldsm_x2(bl[nt][0], bl[nt][1], bBl + off);
            }
#pragma unroll
            for (int mt = 0; mt < 4; mt++) {
                uint32_t off = (uint32_t)((m_base + mt * 16 + arow_off) * PAD_K + kb + akcol) * 2;
                uint32_t a0, a1, a2, a3, e0, e1, e2, e3;
                ldsm_x4(a0, a1, a2, a3, bAh + off);
                ldsm_x4(e0, e1, e2, e3, bAl + off);
#pragma unroll
                for (int nt = 0; nt < 4; nt++) {
                    mma_bf16(c[mt][nt], a0, a1, a2, a3, bh[nt][0], bh[nt][1]);
                    mma_bf16(c[mt][nt], a0, a1, a2, a3, bl[nt][0], bl[nt][1]);
                    mma_bf16(c[mt][nt], e0, e1, e2, e3, bh[nt][0], bh[nt][1]);
                }
            }
        }
        __syncthreads();
    }

    int g  = lane >> 2;
    int tg = lane & 3;
#pragma unroll
    for (int mt = 0; mt < 4; mt++) {
        int r_lo = row0 + m_base + mt * 16 + g;
        int r_hi = r_lo + 8;
#pragma unroll
        for (int nt = 0; nt < 4; nt++) {
            int col = col0 + n_base + nt * 8 + 2 * tg;
            if (r_lo < M) *(float2*)(C + (size_t)r_lo * FDIM + col) = make_float2(c[mt][nt][0], c[mt][nt][1]);
            if (r_hi < M) *(float2*)(C + (size_t)r_hi * FDIM + col) = make_float2(c[mt][nt][2], c[mt][nt][3]);
        }
    }
}

// ---------------- Wc = W2 @ Wl halves  (+ bc = b2 @ Wl halves) --------------------
__global__ void wc_kernel(const float* __restrict__ W2, const float* __restrict__ Wl,
                          const float* __restrict__ b2,
                          float* __restrict__ Wc, float* __restrict__ bc)
{
    int t = threadIdx.x + blockIdx.x * blockDim.x;    // 0..1023
    if (t < 1024) {
        int half = t >> 9;
        int rem  = t & 511;
        int k    = rem >> 1;
        int j    = rem & 1;
        float s = 0.f;
        const float* w2row = W2 + (size_t)k * 256;
        const float* wl    = Wl + (size_t)half * 256 * 2 + j;
        for (int m = 0; m < 256; m++) s = fmaf(w2row[m], wl[2 * m], s);
        Wc[k * 4 + half * 2 + j] = s;
    }
    if (t < 4) {
        int half = t >> 1, j = t & 1;
        float s = 0.f;
        const float* wl = Wl + (size_t)half * 256 * 2 + j;
        for (int m = 0; m < 256; m++) s = fmaf(b2[m], wl[2 * m], s);
        bc[t] = s;
    }
}

// ---- fused aggregate + relu + projection: Q[n] = relu(b1 + S h)[n] @ Wc ----------
__global__ __launch_bounds__(256)
void aggregate_relu_proj_kernel(const float* __restrict__ h,
                                const int* __restrict__ offsets,
                                const int2* __restrict__ edges,
                                const float* __restrict__ bias,
                                const float* __restrict__ Wc,
                                float* __restrict__ Q)
{
    __shared__ float4 sWc[256];
    for (int i = threadIdx.x; i < 256; i += blockDim.x) sWc[i] = ((const float4*)Wc)[i];
    __syncthreads();

    int warp = (blockIdx.x * blockDim.x + threadIdx.x) >> 5;
    int lane = threadIdx.x & 31;
    if (warp >= N_NODES) return;

    int beg = offsets[warp];
    int end = offsets[warp + 1];

    const float4* b4 = (const float4*)bias;
    float4 acc0 = b4[lane];
    float4 acc1 = b4[lane + 32];
    const float4* h4 = (const float4*)h;

#pragma unroll 4
    for (int e = beg; e < end; e++) {
        int2  ed = edges[e];
        float we = __int_as_float(ed.y);
        const float4* hr = h4 + (size_t)ed.x * (FDIM / 4);
        float4 v0 = hr[lane];
        float4 v1 = hr[lane + 32];
        acc0.x = fmaf(we, v0.x, acc0.x); acc0.y = fmaf(we, v0.y, acc0.y);
        acc0.z = fmaf(we, v0.z, acc0.z); acc0.w = fmaf(we, v0.w, acc0.w);
        acc1.x = fmaf(we, v1.x, acc1.x); acc1.y = fmaf(we, v1.y, acc1.y);
        acc1.z = fmaf(we, v1.z, acc1.z); acc1.w = fmaf(we, v1.w, acc1.w);
    }
    acc0.x = fmaxf(acc0.x, 0.f); acc0.y = fmaxf(acc0.y, 0.f);
    acc0.z = fmaxf(acc0.z, 0.f); acc0.w = fmaxf(acc0.w, 0.f);
    acc1.x = fmaxf(acc1.x, 0.f); acc1.y = fmaxf(acc1.y, 0.f);
    acc1.z = fmaxf(acc1.z, 0.f); acc1.w = fmaxf(acc1.w, 0.f);

    float p0 = 0.f, p1 = 0.f, p2 = 0.f, p3 = 0.f;
    const float* a = &acc0.x;
#pragma unroll
    for (int i = 0; i < 4; i++) {
        float4 w = sWc[4 * lane + i];
        p0 = fmaf(a[i], w.x, p0); p1 = fmaf(a[i], w.y, p1);
        p2 = fmaf(a[i], w.z, p2); p3 = fmaf(a[i], w.w, p3);
    }
    const float* b = &acc1.x;
#pragma unroll
    for (int i = 0; i < 4; i++) {
        float4 w = sWc[128 + 4 * lane + i];
        p0 = fmaf(b[i], w.x, p0); p1 = fmaf(b[i], w.y, p1);
        p2 = fmaf(b[i], w.z, p2); p3 = fmaf(b[i], w.w, p3);
    }
#pragma unroll
    for (int off = 16; off > 0; off >>= 1) {
        p0 += __shfl_down_sync(0xFFFFFFFFu, p0, off);
        p1 += __shfl_down_sync(0xFFFFFFFFu, p1, off);
        p2 += __shfl_down_sync(0xFFFFFFFFu, p2, off);
        p3 += __shfl_down_sync(0xFFFFFFFFu, p3, off);
    }
    if (lane == 0) {
        ((float4*)Q)[warp] = make_float4(p0, p1, p2, p3);
    }
}

// ---------------- P[n] = bc + sum_e w_e * Q[src_e] ----------------
__global__ __launch_bounds__(256)
void aggregate_P_kernel(const float* __restrict__ Q,
                        const int* __restrict__ offsets,
                        const int2* __restrict__ edges,
                        const float* __restrict__ bc,
                        float* __restrict__ P)
{
    int warp = (blockIdx.x * blockDim.x + threadIdx.x) >> 5;
    int lane = threadIdx.x & 31;
    if (warp >= N_NODES) return;

    int beg = offsets[warp];
    int end = offsets[warp + 1];

    float4 acc = make_float4(0.f, 0.f, 0.f, 0.f);
    const float4* Q4 = (const float4*)Q;

    for (int e = beg + lane; e < end; e += 32) {
        int2  ed = edges[e];
        float we = __int_as_float(ed.y);
        float4 q = Q4[ed.x];
        acc.x = fmaf(we, q.x, acc.x); acc.y = fmaf(we, q.y, acc.y);
        acc.z = fmaf(we, q.z, acc.z); acc.w = fmaf(we, q.w, acc.w);
    }
#pragma unroll
    for (int off = 16; off > 0; off >>= 1) {
        acc.x += __shfl_down_sync(0xFFFFFFFFu, acc.x, off);
        acc.y += __shfl_down_sync(0xFFFFFFFFu, acc.y, off);
        acc.z += __shfl_down_sync(0xFFFFFFFFu, acc.z, off);
        acc.w += __shfl_down_sync(0xFFFFFFFFu, acc.w, off);
    }
    if (lane == 0) {
        float4 b = *(const float4*)bc;
        ((float4*)P)[warp] = make_float4(acc.x + b.x, acc.y + b.y, acc.z + b.z, acc.w + b.w);
    }
}

// ---------------- final ----------------
__global__ __launch_bounds__(256)
void final_kernel(const float* __restrict__ P,
                  const int* __restrict__ q,
                  const float* __restrict__ bl,
                  float* __restrict__ out)
{
    int i = blockIdx.x * blockDim.x + threadIdx.x;
    if (i >= N_QUERY) return;
    int qa = q[2 * i];
    int qb = q[2 * i + 1];
    float4 Pa = ((const float4*)P)[qa];
    float4 Pb = ((const float4*)P)[qb];
    float l0 = Pa.x + Pb.z + bl[0];
    float l1 = Pa.y + Pb.w + bl[1];
    float m  = fmaxf(l0, l1);
    float lse = m + logf(expf(l0 - m) + expf(l1 - m));
    out[2 * i]     = l0 - lse;
    out[2 * i + 1] = l1 - lse;
}

// ---------------- launch ----------------
extern "C" void kernel_launch(void* const* d_in, const int* in_sizes, int n_in,
                              void* d_out, int out_size)
{
    const float* x    = (const float*)d_in[0];
    const int*   ei   = (const int*)  d_in[1];
    const int*   qe   = (const int*)  d_in[2];
    const float* ew   = (const float*)d_in[3];
    const float* W1   = (const float*)d_in[4];
    const float* b1   = (const float*)d_in[5];
    const float* W2   = (const float*)d_in[6];
    const float* b2   = (const float*)d_in[7];
    const float* Wl   = (const float*)d_in[8];
    const float* bl   = (const float*)d_in[9];
    float*       out  = (float*)d_out;

    float *h, *Q, *P, *Wc, *bc;
    __nv_bfloat16 *w1hi, *w1lo;
    int *counts, *cursor, *offsets, *blocksums;
    int2 *edges;
    cudaGetSymbolAddress((void**)&h,        g_h);
    cudaGetSymbolAddress((void**)&w1hi,     g_w1hi);
    cudaGetSymbolAddress((void**)&w1lo,     g_w1lo);
    cudaGetSymbolAddress((void**)&Q,        g_Q);
    cudaGetSymbolAddress((void**)&P,        g_P);
    cudaGetSymbolAddress((void**)&Wc,       g_Wc);
    cudaGetSymbolAddress((void**)&bc,       g_bc);
    cudaGetSymbolAddress((void**)&counts,   g_counts);
    cudaGetSymbolAddress((void**)&cursor,   g_cursor);
    cudaGetSymbolAddress((void**)&offsets,  g_offsets);
    cudaGetSymbolAddress((void**)&blocksums,g_blocksums);
    cudaGetSymbolAddress((void**)&edges,    g_edges);

    // ---- fork a side stream: split_w first (gemm dep), then CSR + Wc ----
    cudaStream_t s2;
    cudaStreamCreateWithFlags(&s2, cudaStreamNonBlocking);
    cudaEvent_t e0, e1, e2;
    cudaEventCreateWithFlags(&e0, cudaEventDisableTiming);
    cudaEventCreateWithFlags(&e1, cudaEventDisableTiming);
    cudaEventCreateWithFlags(&e2, cudaEventDisableTiming);

    cudaEventRecord(e0, 0);
    cudaStreamWaitEvent(s2, e0, 0);

    split_w_kernel<<<256, 256, 0, s2>>>(W1, w1hi, w1lo);
    cudaEventRecord(e2, s2);                      // gemm dependency

    zero_kernel<<<(N_NODES + 255) / 256, 256, 0, s2>>>(counts, cursor);
    count_kernel<<<(N_EDGES + 255) / 256, 256, 0, s2>>>(ei, counts);
    scan_part1<<<NB_SCAN, 256, 0, s2>>>(counts, offsets, blocksums);
    scan_part2<<<1, 256, 0, s2>>>(blocksums);
    scan_part3<<<NB_SCAN, 256, 0, s2>>>(offsets, blocksums);
    fill_kernel<<<(N_EDGES + 255) / 256, 256, 0, s2>>>(ei, ew, offsets, cursor, edges);
    wc_kernel<<<4, 256, 0, s2>>>(W2, Wl, b2, Wc, bc);
    cudaEventRecord(e1, s2);

    // main stream: GEMM (conv1, fused x split)
    cudaStreamWaitEvent(0, e2, 0);
    dim3 gemm_grid((N_NODES + 127) / 128, 2);
    gemm_hmma<<<gemm_grid, 256>>>(x, w1hi, w1lo, h, N_NODES);

    // join: aggregates need edges/offsets/Wc
    cudaStreamWaitEvent(0, e1, 0);

    const int agg_grid = (N_NODES * 32 + 255) / 256;
    aggregate_relu_proj_kernel<<<agg_grid, 256>>>(h, offsets, edges, b1, Wc, Q);
    aggregate_P_kernel<<<agg_grid, 256>>>(Q, offsets, edges, bc, P);
    final_kernel<<<(N_QUERY + 255) / 256, 256>>>(P, qe, bl, out);
}

// round 12
// speedup vs baseline: 1.5719x; 1.5719x over previous
#include <cuda_runtime.h>
#include <cuda_bf16.h>
#include <math.h>
#include <stdint.h>

#define N_NODES  50000
#define N_EDGES  1000000
#define N_QUERY  100000
#define FDIM     256
#define KDIM     256
#define NB_SCAN  ((N_NODES + 255) / 256)   // 196

// ---------------- scratch (device globals: allocation-free) ----------------
__device__ float g_h[(size_t)N_NODES * FDIM];          // x @ W1
__device__ __nv_bfloat16 g_w1hi[KDIM * KDIM];          // W1^T [n][k]
__device__ __nv_bfloat16 g_w1lo[KDIM * KDIM];
__device__ float g_Q[(size_t)N_NODES * 4];
__device__ float g_P[(size_t)N_NODES * 4];
__device__ float g_Wc[256 * 4];
__device__ float g_bc[4];
__device__ int   g_counts[N_NODES];
__device__ int   g_cursor[N_NODES];
__device__ int   g_offsets[N_NODES + 1];
__device__ int   g_blocksums[NB_SCAN];
__device__ int2  g_edges[N_EDGES];

// ---------------- CSR build ----------------
__global__ void zero_kernel(int* __restrict__ counts, int* __restrict__ cursor)
{
    int i = blockIdx.x * blockDim.x + threadIdx.x;
    if (i < N_NODES) { counts[i] = 0; cursor[i] = 0; }
}

__global__ void count_kernel(const int* __restrict__ edge_index, int* __restrict__ counts)
{
    int e = blockIdx.x * blockDim.x + threadIdx.x;
    if (e < N_EDGES) atomicAdd(&counts[edge_index[N_EDGES + e]], 1);
}

__global__ void scan_part1(const int* __restrict__ counts, int* __restrict__ offsets,
                           int* __restrict__ blocksums)
{
    __shared__ int s[256];
    int i = blockIdx.x * 256 + threadIdx.x;
    int v = (i < N_NODES) ? counts[i] : 0;
    s[threadIdx.x] = v;
    __syncthreads();
    for (int off = 1; off < 256; off <<= 1) {
        int t = (threadIdx.x >= off) ? s[threadIdx.x - off] : 0;
        __syncthreads();
        s[threadIdx.x] += t;
        __syncthreads();
    }
    if (i < N_NODES) offsets[i] = s[threadIdx.x] - v;
    if (threadIdx.x == 255) blocksums[blockIdx.x] = s[255];
}

__global__ void scan_part2(int* __restrict__ blocksums)
{
    __shared__ int s[256];
    int i = threadIdx.x;
    int v = (i < NB_SCAN) ? blocksums[i] : 0;
    s[i] = v;
    __syncthreads();
    for (int off = 1; off < 256; off <<= 1) {
        int t = (i >= off) ? s[i - off] : 0;
        __syncthreads();
        s[i] += t;
        __syncthreads();
    }
    if (i < NB_SCAN) blocksums[i] = s[i] - v;
}

__global__ void scan_part3(int* __restrict__ offsets, const int* __restrict__ blocksums)
{
    int i = blockIdx.x * 256 + threadIdx.x;
    if (i < N_NODES) offsets[i] += blocksums[blockIdx.x];
    if (i == 0) offsets[N_NODES] = N_EDGES;
}

__global__ void fill_kernel(const int* __restrict__ edge_index,
                            const float* __restrict__ w,
                            const int* __restrict__ offsets,
                            int* __restrict__ cursor,
                            int2* __restrict__ edges)
{
    int e = blockIdx.x * blockDim.x + threadIdx.x;
    if (e >= N_EDGES) return;
    int s = edge_index[e];
    int d = edge_index[N_EDGES + e];
    int p = offsets[d] + atomicAdd(&cursor[d], 1);
    edges[p] = make_int2(s, __float_as_int(w[e]));
}

// ---------------- W1 [k][n] -> Wt [n][k] bf16 hi/lo ----------------
__global__ void split_w_kernel(const float* __restrict__ W,
                               __nv_bfloat16* __restrict__ bhi,
                               __nv_bfloat16* __restrict__ blo)
{
    int idx = blockIdx.x * 256 + threadIdx.x;   // n*256 + k
    int n = idx >> 8, k = idx & 255;
    float v = W[k * 256 + n];
    __nv_bfloat16 h = __float2bfloat16(v);
    bhi[idx] = h;
    blo[idx] = __float2bfloat16(v - __bfloat162float(h));
}

// ---------------- HMMA split-bf16 GEMM with fused fp32->hi/lo A conversion --------
// (R10 version — verified 217.5us total; scalar LDS frag loads, no staging regs)
#define PAD_K 40

__device__ __forceinline__ void mma_bf16(float* c, uint32_t a0, uint32_t a1,
                                         uint32_t a2, uint32_t a3,
                                         uint32_t b0, uint32_t b1) {
    asm volatile("mma.sync.aligned.m16n8k16.row.col.f32.bf16.bf16.f32 "
                 "{%0,%1,%2,%3}, {%4,%5,%6,%7}, {%8,%9}, {%0,%1,%2,%3};"
                 : "+f"(c[0]), "+f"(c[1]), "+f"(c[2]), "+f"(c[3])
                 : "r"(a0), "r"(a1), "r"(a2), "r"(a3), "r"(b0), "r"(b1));
}

__global__ __launch_bounds__(256)
void gemm_hmma(const float* __restrict__ X,
               const __nv_bfloat16* __restrict__ Bhi, const __nv_bfloat16* __restrict__ Blo,
               float* __restrict__ C, int M)
{
    __shared__ __nv_bfloat16 sAh[128 * PAD_K];
    __shared__ __nv_bfloat16 sAl[128 * PAD_K];
    __shared__ __nv_bfloat16 sBh[128 * PAD_K];
    __shared__ __nv_bfloat16 sBl[128 * PAD_K];

    int tid  = threadIdx.x;
    int wid  = tid >> 5;
    int lane = tid & 31;
    int g    = lane >> 2;
    int tg   = lane & 3;

    int row0 = blockIdx.x * 128;
    int col0 = blockIdx.y * 128;

    int wmi = wid & 1;
    int wni = wid >> 1;
    int m_base = wmi * 64;
    int n_base = wni * 32;

    float c[4][4][4];
#pragma unroll
    for (int mt = 0; mt < 4; mt++)
#pragma unroll
        for (int nt = 0; nt < 4; nt++)
#pragma unroll
            for (int j = 0; j < 4; j++) c[mt][nt][j] = 0.f;

    for (int k0 = 0; k0 < KDIM; k0 += 32) {
        // ---- B halves: 128 rows x 4 uint4 per half; 2 uint4 per thread per half ----
#pragma unroll
        for (int r = 0; r < 2; r++) {
            int i   = tid + r * 256;           // 0..511
            int row = i >> 2, u = i & 3;
            const uint4* gBh = (const uint4*)(Bhi + (size_t)(col0 + row) * KDIM + k0);
            const uint4* gBl = (const uint4*)(Blo + (size_t)(col0 + row) * KDIM + k0);
            *(uint4*)(sBh + row * PAD_K + u * 8) = gBh[u];
            *(uint4*)(sBl + row * PAD_K + u * 8) = gBl[u];
        }
        // ---- A: read x fp32 and split to hi/lo bf16 while staging ----
#pragma unroll
        for (int r = 0; r < 4; r++) {
            int i   = tid + r * 256;           // 0..1023
            int row = i >> 3, u = i & 7;       // u: float4 unit (4 floats)
            int grow = row0 + row;
            float4 v = (grow < M) ? *(const float4*)(X + (size_t)grow * KDIM + k0 + u * 4)
                                  : make_float4(0.f, 0.f, 0.f, 0.f);
            __nv_bfloat16 h0 = __float2bfloat16(v.x), h1 = __float2bfloat16(v.y);
            __nv_bfloat16 h2 = __float2bfloat16(v.z), h3 = __float2bfloat16(v.w);
            __nv_bfloat16 l0 = __float2bfloat16(v.x - __bfloat162float(h0));
            __nv_bfloat16 l1 = __float2bfloat16(v.y - __bfloat162float(h1));
            __nv_bfloat16 l2 = __float2bfloat16(v.z - __bfloat162float(h2));
            __nv_bfloat16 l3 = __float2bfloat16(v.w - __bfloat162float(h3));
            __nv_bfloat162* ah = (__nv_bfloat162*)(sAh + row * PAD_K + u * 4);
            __nv_bfloat162* al = (__nv_bfloat162*)(sAl + row * PAD_K + u * 4);
            ah[0] = __nv_bfloat162(h0, h1);
            ah[1] = __nv_bfloat162(h2, h3);
            al[0] = __nv_bfloat162(l0, l1);
            al[1] = __nv_bfloat162(l2, l3);
        }
        __syncthreads();

#pragma unroll
        for (int kk = 0; kk < 2; kk++) {
            int kb = kk * 16;
            uint32_t bh[4][2], bl[4][2];
#pragma unroll
            for (int nt = 0; nt < 4; nt++) {
                const __nv_bfloat16* bp = sBh + (n_base + nt * 8 + g) * PAD_K + kb + 2 * tg;
                const __nv_bfloat16* lp = sBl + (n_base + nt * 8 + g) * PAD_K + kb + 2 * tg;
                bh[nt][0] = *(const uint32_t*)bp;
                bh[nt][1] = *(const uint32_t*)(bp + 8);
                bl[nt][0] = *(const uint32_t*)lp;
                bl[nt][1] = *(const uint32_t*)(lp + 8);
            }
#pragma unroll
            for (int mt = 0; mt < 4; mt++) {
                int ar = m_base + mt * 16;
                const __nv_bfloat16* ah = sAh + (ar + g) * PAD_K + kb + 2 * tg;
                const __nv_bfloat16* al = sAl + (ar + g) * PAD_K + kb + 2 * tg;
                uint32_t a0 = *(const uint32_t*)ah;
                uint32_t a1 = *(const uint32_t*)(ah + 8 * PAD_K);
                uint32_t a2 = *(const uint32_t*)(ah + 8);
                uint32_t a3 = *(const uint32_t*)(ah + 8 * PAD_K + 8);
                uint32_t e0 = *(const uint32_t*)al;
                uint32_t e1 = *(const uint32_t*)(al + 8 * PAD_K);
                uint32_t e2 = *(const uint32_t*)(al + 8);
                uint32_t e3 = *(const uint32_t*)(al + 8 * PAD_K + 8);
#pragma unroll
                for (int nt = 0; nt < 4; nt++) {
                    mma_bf16(c[mt][nt], a0, a1, a2, a3, bh[nt][0], bh[nt][1]);
                    mma_bf16(c[mt][nt], a0, a1, a2, a3, bl[nt][0], bl[nt][1]);
                    mma_bf16(c[mt][nt], e0, e1, e2, e3, bh[nt][0], bh[nt][1]);
                }
            }
        }
        __syncthreads();
    }

#pragma unroll
    for (int mt = 0; mt < 4; mt++) {
        int r_lo = row0 + m_base + mt * 16 + g;
        int r_hi = r_lo + 8;
#pragma unroll
        for (int nt = 0; nt < 4; nt++) {
            int col = col0 + n_base + nt * 8 + 2 * tg;
            if (r_lo < M) *(float2*)(C + (size_t)r_lo * FDIM + col) = make_float2(c[mt][nt][0], c[mt][nt][1]);
            if (r_hi < M) *(float2*)(C + (size_t)r_hi * FDIM + col) = make_float2(c[mt][nt][2], c[mt][nt][3]);
        }
    }
}

// ---------------- Wc = W2 @ Wl halves  (+ bc = b2 @ Wl halves) --------------------
__global__ void wc_kernel(const float* __restrict__ W2, const float* __restrict__ Wl,
                          const float* __restrict__ b2,
                          float* __restrict__ Wc, float* __restrict__ bc)
{
    int t = threadIdx.x + blockIdx.x * blockDim.x;    // 0..1023
    if (t < 1024) {
        int half = t >> 9;
        int rem  = t & 511;
        int k    = rem >> 1;
        int j    = rem & 1;
        float s = 0.f;
        const float* w2row = W2 + (size_t)k * 256;
        const float* wl    = Wl + (size_t)half * 256 * 2 + j;
        for (int m = 0; m < 256; m++) s = fmaf(w2row[m], wl[2 * m], s);
        Wc[k * 4 + half * 2 + j] = s;
    }
    if (t < 4) {
        int half = t >> 1, j = t & 1;
        float s = 0.f;
        const float* wl = Wl + (size_t)half * 256 * 2 + j;
        for (int m = 0; m < 256; m++) s = fmaf(b2[m], wl[2 * m], s);
        bc[t] = s;
    }
}

// ---- fused aggregate + relu + projection: Q[n] = relu(b1 + S h)[n] @ Wc ----------
__global__ __launch_bounds__(256)
void aggregate_relu_proj_kernel(const float* __restrict__ h,
                                const int* __restrict__ offsets,
                                const int2* __restrict__ edges,
                                const float* __restrict__ bias,
                                const float* __restrict__ Wc,
                                float* __restrict__ Q)
{
    __shared__ float4 sWc[256];
    for (int i = threadIdx.x; i < 256; i += blockDim.x) sWc[i] = ((const float4*)Wc)[i];
    __syncthreads();

    int warp = (blockIdx.x * blockDim.x + threadIdx.x) >> 5;
    int lane = threadIdx.x & 31;
    if (warp >= N_NODES) return;

    int beg = offsets[warp];
    int end = offsets[warp + 1];

    const float4* b4 = (const float4*)bias;
    float4 acc0 = b4[lane];
    float4 acc1 = b4[lane + 32];
    const float4* h4 = (const float4*)h;

#pragma unroll 4
    for (int e = beg; e < end; e++) {
        int2  ed = edges[e];
        float we = __int_as_float(ed.y);
        const float4* hr = h4 + (size_t)ed.x * (FDIM / 4);
        float4 v0 = hr[lane];
        float4 v1 = hr[lane + 32];
        acc0.x = fmaf(we, v0.x, acc0.x); acc0.y = fmaf(we, v0.y, acc0.y);
        acc0.z = fmaf(we, v0.z, acc0.z); acc0.w = fmaf(we, v0.w, acc0.w);
        acc1.x = fmaf(we, v1.x, acc1.x); acc1.y = fmaf(we, v1.y, acc1.y);
        acc1.z = fmaf(we, v1.z, acc1.z); acc1.w = fmaf(we, v1.w, acc1.w);
    }
    acc0.x = fmaxf(acc0.x, 0.f); acc0.y = fmaxf(acc0.y, 0.f);
    acc0.z = fmaxf(acc0.z, 0.f); acc0.w = fmaxf(acc0.w, 0.f);
    acc1.x = fmaxf(acc1.x, 0.f); acc1.y = fmaxf(acc1.y, 0.f);
    acc1.z = fmaxf(acc1.z, 0.f); acc1.w = fmaxf(acc1.w, 0.f);

    float p0 = 0.f, p1 = 0.f, p2 = 0.f, p3 = 0.f;
    const float* a = &acc0.x;
#pragma unroll
    for (int i = 0; i < 4; i++) {
        float4 w = sWc[4 * lane + i];
        p0 = fmaf(a[i], w.x, p0); p1 = fmaf(a[i], w.y, p1);
        p2 = fmaf(a[i], w.z, p2); p3 = fmaf(a[i], w.w, p3);
    }
    const float* b = &acc1.x;
#pragma unroll
    for (int i = 0; i < 4; i++) {
        float4 w = sWc[128 + 4 * lane + i];
        p0 = fmaf(b[i], w.x, p0); p1 = fmaf(b[i], w.y, p1);
        p2 = fmaf(b[i], w.z, p2); p3 = fmaf(b[i], w.w, p3);
    }
#pragma unroll
    for (int off = 16; off > 0; off >>= 1) {
        p0 += __shfl_down_sync(0xFFFFFFFFu, p0, off);
        p1 += __shfl_down_sync(0xFFFFFFFFu, p1, off);
        p2 += __shfl_down_sync(0xFFFFFFFFu, p2, off);
        p3 += __shfl_down_sync(0xFFFFFFFFu, p3, off);
    }
    if (lane == 0) {
        ((float4*)Q)[warp] = make_float4(p0, p1, p2, p3);
    }
}

// ---------------- P[n] = bc + sum_e w_e * Q[src_e] ----------------
__global__ __launch_bounds__(256)
void aggregate_P_kernel(const float* __restrict__ Q,
                        const int* __restrict__ offsets,
                        const int2* __restrict__ edges,
                        const float* __restrict__ bc,
                        float* __restrict__ P)
{
    int warp = (blockIdx.x * blockDim.x + threadIdx.x) >> 5;
    int lane = threadIdx.x & 31;
    if (warp >= N_NODES) return;

    int beg = offsets[warp];
    int end = offsets[warp + 1];

    float4 acc = make_float4(0.f, 0.f, 0.f, 0.f);
    const float4* Q4 = (const float4*)Q;

    for (int e = beg + lane; e < end; e += 32) {
        int2  ed = edges[e];
        float we = __int_as_float(ed.y);
        float4 q = Q4[ed.x];
        acc.x = fmaf(we, q.x, acc.x); acc.y = fmaf(we, q.y, acc.y);
        acc.z = fmaf(we, q.z, acc.z); acc.w = fmaf(we, q.w, acc.w);
    }
#pragma unroll
    for (int off = 16; off > 0; off >>= 1) {
        acc.x += __shfl_down_sync(0xFFFFFFFFu, acc.x, off);
        acc.y += __shfl_down_sync(0xFFFFFFFFu, acc.y, off);
        acc.z += __shfl_down_sync(0xFFFFFFFFu, acc.z, off);
        acc.w += __shfl_down_sync(0xFFFFFFFFu, acc.w, off);
    }
    if (lane == 0) {
        float4 b = *(const float4*)bc;
        ((float4*)P)[warp] = make_float4(acc.x + b.x, acc.y + b.y, acc.z + b.z, acc.w + b.w);
    }
}

// ---------------- final ----------------
__global__ __launch_bounds__(256)
void final_kernel(const float* __restrict__ P,
                  const int* __restrict__ q,
                  const float* __restrict__ bl,
                  float* __restrict__ out)
{
    int i = blockIdx.x * blockDim.x + threadIdx.x;
    if (i >= N_QUERY) return;
    int qa = q[2 * i];
    int qb = q[2 * i + 1];
    float4 Pa = ((const float4*)P)[qa];
    float4 Pb = ((const float4*)P)[qb];
    float l0 = Pa.x + Pb.z + bl[0];
    float l1 = Pa.y + Pb.w + bl[1];
    float m  = fmaxf(l0, l1);
    float lse = m + logf(expf(l0 - m) + expf(l1 - m));
    out[2 * i]     = l0 - lse;
    out[2 * i + 1] = l1 - lse;
}

// ---------------- launch ----------------
extern "C" void kernel_launch(void* const* d_in, const int* in_sizes, int n_in,
                              void* d_out, int out_size)
{
    const float* x    = (const float*)d_in[0];
    const int*   ei   = (const int*)  d_in[1];
    const int*   qe   = (const int*)  d_in[2];
    const float* ew   = (const float*)d_in[3];
    const float* W1   = (const float*)d_in[4];
    const float* b1   = (const float*)d_in[5];
    const float* W2   = (const float*)d_in[6];
    const float* b2   = (const float*)d_in[7];
    const float* Wl   = (const float*)d_in[8];
    const float* bl   = (const float*)d_in[9];
    float*       out  = (float*)d_out;

    float *h, *Q, *P, *Wc, *bc;
    __nv_bfloat16 *w1hi, *w1lo;
    int *counts, *cursor, *offsets, *blocksums;
    int2 *edges;
    cudaGetSymbolAddress((void**)&h,        g_h);
    cudaGetSymbolAddress((void**)&w1hi,     g_w1hi);
    cudaGetSymbolAddress((void**)&w1lo,     g_w1lo);
    cudaGetSymbolAddress((void**)&Q,        g_Q);
    cudaGetSymbolAddress((void**)&P,        g_P);
    cudaGetSymbolAddress((void**)&Wc,       g_Wc);
    cudaGetSymbolAddress((void**)&bc,       g_bc);
    cudaGetSymbolAddress((void**)&counts,   g_counts);
    cudaGetSymbolAddress((void**)&cursor,   g_cursor);
    cudaGetSymbolAddress((void**)&offsets,  g_offsets);
    cudaGetSymbolAddress((void**)&blocksums,g_blocksums);
    cudaGetSymbolAddress((void**)&edges,    g_edges);

    // ---- fork a side stream: split_w first (gemm dep), then CSR + Wc ----
    cudaStream_t s2;
    cudaStreamCreateWithFlags(&s2, cudaStreamNonBlocking);
    cudaEvent_t e0, e1, e2;
    cudaEventCreateWithFlags(&e0, cudaEventDisableTiming);
    cudaEventCreateWithFlags(&e1, cudaEventDisableTiming);
    cudaEventCreateWithFlags(&e2, cudaEventDisableTiming);

    cudaEventRecord(e0, 0);
    cudaStreamWaitEvent(s2, e0, 0);

    split_w_kernel<<<256, 256, 0, s2>>>(W1, w1hi, w1lo);
    cudaEventRecord(e2, s2);                      // gemm dependency

    zero_kernel<<<(N_NODES + 255) / 256, 256, 0, s2>>>(counts, cursor);
    count_kernel<<<(N_EDGES + 255) / 256, 256, 0, s2>>>(ei, counts);
    scan_part1<<<NB_SCAN, 256, 0, s2>>>(counts, offsets, blocksums);
    scan_part2<<<1, 256, 0, s2>>>(blocksums);
    scan_part3<<<NB_SCAN, 256, 0, s2>>>(offsets, blocksums);
    fill_kernel<<<(N_EDGES + 255) / 256, 256, 0, s2>>>(ei, ew, offsets, cursor, edges);
    wc_kernel<<<4, 256, 0, s2>>>(W2, Wl, b2, Wc, bc);
    cudaEventRecord(e1, s2);

    // main stream: GEMM (conv1, fused x split)
    cudaStreamWaitEvent(0, e2, 0);
    dim3 gemm_grid((N_NODES + 127) / 128, 2);
    gemm_hmma<<<gemm_grid, 256>>>(x, w1hi, w1lo, h, N_NODES);

    // join: aggregates need edges/offsets/Wc
    cudaStreamWaitEvent(0, e1, 0);

    const int agg_grid = (N_NODES * 32 + 255) / 256;
    aggregate_relu_proj_kernel<<<agg_grid, 256>>>(h, offsets, edges, b1, Wc, Q);
    aggregate_P_kernel<<<agg_grid, 256>>>(Q, offsets, edges, bc, P);
    final_kernel<<<(N_QUERY + 255) / 256, 256>>>(P, qe, bl, out);
}